// round 14
// baseline (speedup 1.0000x reference)
#include <cuda_runtime.h>
#include <cuda_fp16.h>
#include <cstdint>

typedef unsigned short ushort_t;

// Problem constants
#define WSZ   64
#define NC    48
#define NT    3
#define NB    4
#define IMG   512
#define KTOT  (NT*NC)            // 144
#define NWIN  (NB*8*8)           // 256

// G scratch, single fp16 plane: [win][k=(t*48+c)][n=H'*64+W']
__device__ __align__(16) ushort_t Gf[(size_t)NWIN * KTOT * 4096];

// Pre-transposed factors, single fp16: [t][n][k]
__device__ __align__(16) ushort_t FWs[NT*WSZ*WSZ];
__device__ __align__(16) ushort_t FHs[NT*WSZ*WSZ];
// Cs^T single fp16: [C'][k=t*48+c]
__device__ __align__(16) ushort_t CsTh[NC*KTOT];

// ---------------------------------------------------------------------------
// helpers
// ---------------------------------------------------------------------------
__device__ __forceinline__ uint32_t smem_u32(const void* p) {
    uint32_t a;
    asm("{ .reg .u64 t; cvta.to.shared.u64 t, %1; cvt.u32.u64 %0, t; }"
        : "=r"(a) : "l"(p));
    return a;
}
__device__ __forceinline__ void ldsm4(uint32_t* r, uint32_t addr) {
    asm volatile("ldmatrix.sync.aligned.m8n8.x4.shared.b16 {%0,%1,%2,%3}, [%4];"
                 : "=r"(r[0]), "=r"(r[1]), "=r"(r[2]), "=r"(r[3]) : "r"(addr));
}
__device__ __forceinline__ void ldsm4t(uint32_t* r, uint32_t addr) {
    asm volatile("ldmatrix.sync.aligned.m8n8.x4.trans.shared.b16 {%0,%1,%2,%3}, [%4];"
                 : "=r"(r[0]), "=r"(r[1]), "=r"(r[2]), "=r"(r[3]) : "r"(addr));
}
__device__ __forceinline__ void mma16816h(float* d, const uint32_t* a,
                                          uint32_t b0, uint32_t b1) {
    asm volatile(
        "mma.sync.aligned.m16n8k16.row.col.f32.f16.f16.f32 "
        "{%0,%1,%2,%3},{%4,%5,%6,%7},{%8,%9},{%0,%1,%2,%3};"
        : "+f"(d[0]), "+f"(d[1]), "+f"(d[2]), "+f"(d[3])
        : "r"(a[0]), "r"(a[1]), "r"(a[2]), "r"(a[3]), "r"(b0), "r"(b1));
}
__device__ __forceinline__ void cpa16(uint32_t dst, const void* src) {
    asm volatile("cp.async.ca.shared.global [%0], [%1], 16;"
                 :: "r"(dst), "l"(src) : "memory");
}
#define CPA_COMMIT() asm volatile("cp.async.commit_group;" ::: "memory")

#define RSTRIDE 144   // smem row stride (bytes per 64-fp16 row)

// Warp GEMM: 32(m) x 32(n) x 64(k), single fp16 A/B, fp32 acc.
__device__ __forceinline__ void gemm32x32(
    uint32_t aA, uint32_t aB, int mrow, int nbase, int lane, float acc[2][4][4])
{
    const int rA = lane & 15;
    const int cA = (lane >> 4) * 8;
    const int mB = lane >> 3;
    const int nB = (mB >> 1) * 8 + (lane & 7);
    const int kB = (mB & 1) * 8;
    const uint32_t pA0 = (uint32_t)((mrow + rA) * RSTRIDE + cA * 2);
    const uint32_t pA1 = pA0 + 16 * RSTRIDE;
    const uint32_t pB0 = (uint32_t)((nbase + nB) * RSTRIDE + kB * 2);
    const uint32_t pB1 = pB0 + 16 * RSTRIDE;

    #pragma unroll
    for (int ks = 0; ks < 4; ks++) {
        const uint32_t ko = ks * 32;
        uint32_t a0[4], a1[4], b0[4], b1[4];
        ldsm4(a0, aA + pA0 + ko);
        ldsm4(a1, aA + pA1 + ko);
        ldsm4(b0, aB + pB0 + ko);
        ldsm4(b1, aB + pB1 + ko);

        mma16816h(acc[0][0], a0, b0[0], b0[1]);
        mma16816h(acc[0][1], a0, b0[2], b0[3]);
        mma16816h(acc[0][2], a0, b1[0], b1[1]);
        mma16816h(acc[0][3], a0, b1[2], b1[3]);
        mma16816h(acc[1][0], a1, b0[0], b0[1]);
        mma16816h(acc[1][1], a1, b0[2], b0[3]);
        mma16816h(acc[1][2], a1, b1[0], b1[1]);
        mma16816h(acc[1][3], a1, b1[2], b1[3]);
    }
}

// ---------------------------------------------------------------------------
// Prep (once, tiny)
// ---------------------------------------------------------------------------
__global__ void k_prep(const float* __restrict__ Ws, const float* __restrict__ Hs,
                       const float* __restrict__ Cs)
{
    int u = blockIdx.x * 256 + threadIdx.x;
    if (u < NT*WSZ*WSZ) {
        int t = u >> 12;
        int r = u & 4095;
        int k = r >> 6;
        int n = r & 63;
        __half w = __float2half_rn(Ws[u]);
        __half h = __float2half_rn(Hs[u]);
        FWs[(t << 12) + n*WSZ + k] = *reinterpret_cast<ushort_t*>(&w);
        FHs[(t << 12) + n*WSZ + k] = *reinterpret_cast<ushort_t*>(&h);
    }
    if (u < KTOT*NC) {
        int k  = u / NC;
        int Cp = u % NC;
        __half v = __float2half_rn(Cs[u]);
        CsTh[Cp*KTOT + k] = *reinterpret_cast<ushort_t*>(&v);
    }
}

// stage12 SMEM (bytes): X4 256 rows, T4 256 rows, FW 64 rows, FH 64 rows
#define OX4  0
#define OT4  36864
#define OFW  73728
#define OFH  82944
#define SM12_TOTAL 92160

// ---------------------------------------------------------------------------
// Stage12 (unchanged from R13)
// ---------------------------------------------------------------------------
__global__ void __launch_bounds__(256) k_stage12(const float* __restrict__ x)
{
    extern __shared__ __align__(16) char smem[];
    const uint32_t S = smem_u32(smem);
    const uint32_t XS = S+OX4, TS = S+OT4, FW = S+OFW, FH = S+OFH;

    const int tid  = threadIdx.x;
    const int lane = tid & 31;
    const int wid  = tid >> 5;
    const int mrow  = (wid >> 2) * 32;
    const int ncol0 = (wid & 3) * 64;

    const int win = blockIdx.x, cq = blockIdx.y, b = blockIdx.z;
    const int q = win & 7, p = win >> 3;
    const int c0 = cq * 4;

    #pragma unroll
    for (int it = 0; it < 16; it++) {
        int u = it*256 + tid;
        int r = u >> 4, w4 = (u & 15) << 2;
        int cc = r >> 6, h = r & 63;
        const float* src = x + (((size_t)(b*NC + c0 + cc)*IMG + p*WSZ + h)*IMG
                                + q*WSZ + w4);
        float4 v = *(const float4*)src;
        __half2 v01 = __floats2half2_rn(v.x, v.y);
        __half2 v23 = __floats2half2_rn(v.z, v.w);
        uint32_t off = (uint32_t)(r*RSTRIDE + w4*2);
        *(uint32_t*)(smem + OX4 + off)     = *(uint32_t*)&v01;
        *(uint32_t*)(smem + OX4 + off + 4) = *(uint32_t*)&v23;
    }

    const size_t winI = (size_t)((b*8 + p)*8 + q);
    const int erow = lane >> 2;
    const int ecol = (lane & 3) * 2;

    for (int t = 0; t < NT; t++) {
        __syncthreads();

        {
            const uint4* sw = (const uint4*)(FWs + (t << 12));
            const uint4* sh = (const uint4*)(FHs + (t << 12));
            #pragma unroll
            for (int i = 0; i < 2; i++) {
                int idx = i*256 + tid;
                uint32_t off = (uint32_t)((idx >> 3)*RSTRIDE + (idx & 7)*16);
                *(uint4*)(smem + OFW + off) = sw[idx];
                *(uint4*)(smem + OFH + off) = sh[idx];
            }
        }
        __syncthreads();

        #pragma unroll
        for (int half = 0; half < 2; half++) {
            const int nbase = ncol0 + half*32;
            float acc[2][4][4];
            #pragma unroll
            for (int a1 = 0; a1 < 2; a1++)
                #pragma unroll
                for (int a2 = 0; a2 < 4; a2++)
                    #pragma unroll
                    for (int a3 = 0; a3 < 4; a3++) acc[a1][a2][a3] = 0.0f;
            gemm32x32(FW, XS, mrow, nbase, lane, acc);

            const int cc = nbase >> 6;
            const int hb = nbase & 63;
            #pragma unroll
            for (int mt = 0; mt < 2; mt++)
                #pragma unroll
                for (int g = 0; g < 4; g++) {
                    int m = mrow + mt*16 + erow;
                    int h = hb + g*8 + ecol;
                    __half2 v01 = __floats2half2_rn(acc[mt][g][0], acc[mt][g][1]);
                    __half2 v23 = __floats2half2_rn(acc[mt][g][2], acc[mt][g][3]);
                    uint32_t o = (uint32_t)((cc*64 + m)*RSTRIDE + h*2);
                    *(uint32_t*)(smem + OT4 + o)             = *(uint32_t*)&v01;
                    *(uint32_t*)(smem + OT4 + o + 8*RSTRIDE) = *(uint32_t*)&v23;
                }
        }
        __syncthreads();

        #pragma unroll
        for (int half = 0; half < 2; half++) {
            const int nbase = ncol0 + half*32;
            float acc[2][4][4];
            #pragma unroll
            for (int a1 = 0; a1 < 2; a1++)
                #pragma unroll
                for (int a2 = 0; a2 < 4; a2++)
                    #pragma unroll
                    for (int a3 = 0; a3 < 4; a3++) acc[a1][a2][a3] = 0.0f;
            gemm32x32(FH, TS, mrow, nbase, lane, acc);

            const int cc = nbase >> 6;
            const int wb = nbase & 63;
            ushort_t* gf = Gf + (winI*KTOT + (size_t)(t*NC + c0 + cc)) * 4096;
            #pragma unroll
            for (int mt = 0; mt < 2; mt++)
                #pragma unroll
                for (int g = 0; g < 4; g++) {
                    int m = mrow + mt*16 + erow;
                    int Wp = wb + g*8 + ecol;
                    __half2 v01 = __floats2half2_rn(acc[mt][g][0], acc[mt][g][1]);
                    __half2 v23 = __floats2half2_rn(acc[mt][g][2], acc[mt][g][3]);
                    *(uint32_t*)&gf[m*WSZ + Wp]     = *(uint32_t*)&v01;
                    *(uint32_t*)&gf[(m+8)*WSZ + Wp] = *(uint32_t*)&v23;
                }
        }
    }
}

// ---------------------------------------------------------------------------
// Stage3: CTA = (window, 1024-n group) = 4 batched 256-n tiles.
// One A load; 36 k-chunks stream through a 4-buffer cp.async pipeline
// (3 in flight) crossing tile boundaries without draining.
// ---------------------------------------------------------------------------
#define ASTR3 336
#define BSTR 528
#define BBUF 8448
#define OA3 0
#define OB3 16128
#define SM3_TOTAL (OB3 + 4*BBUF)   // 49920
#define NCHUNK 36                  // 4 tiles x 9 k-chunks

__global__ void __launch_bounds__(256) k_stage3(float* __restrict__ out)
{
    extern __shared__ __align__(16) char smem[];
    const uint32_t S = smem_u32(smem);
    const uint32_t AH = S+OA3, B0 = S+OB3;

    const int tid  = threadIdx.x;
    const int lane = tid & 31;
    const int wid  = tid >> 5;
    const int win   = blockIdx.y;
    const int gtile = blockIdx.x;         // 0..3 -> n base gtile*1024
    const int nloc = (wid >> 1) * 64 + (wid & 1) * 32;

    // A load once: 48 rows x 18 uint4
    for (int i = tid; i < 864; i += 256) {
        int r = i / 18, u = i % 18;
        *(uint4*)(smem + OA3 + (uint32_t)(r*ASTR3 + u*16)) =
            *(const uint4*)(CsTh + r*KTOT + u*8);
    }

    const ushort_t* gwin = Gf + (size_t)win * KTOT * 4096 + (size_t)gtile * 1024;

    const int k0a = tid >> 5,         lua = tid & 31;
    const int k0b = (tid + 256) >> 5, lub = tid & 31;

    // chunk j: tile = j/9 (n offset tile*256), kc = j%9 (k offset kc*16)
    auto issue = [&](int j) {
        int tile = j / 9, kc = j - tile*9;
        const ushort_t* src = gwin + (size_t)(kc*16) * 4096 + tile*256;
        uint32_t Bd = B0 + (uint32_t)((j & 3) * BBUF);
        cpa16(Bd + (uint32_t)(k0a*BSTR + lua*16), src + (size_t)k0a*4096 + lua*8);
        cpa16(Bd + (uint32_t)(k0b*BSTR + lub*16), src + (size_t)k0b*4096 + lub*8);
        CPA_COMMIT();
    };

    // Prologue: chunks 0,1,2
    issue(0); issue(1); issue(2);
    __syncthreads();   // A visible

    const int rA = lane & 15;
    const int cA = (lane >> 4) * 8;
    const int rB = (lane & 7) + ((lane >> 3) & 1) * 8;
    const int cB = ((lane >> 4) & 1) * 8;

    const int b = win >> 6;
    const int p = (win >> 3) & 7;
    const int q = win & 7;
    const int erow = lane >> 2;
    const int ecol = (lane & 3) * 2;

    float acc[3][4][4];
    #pragma unroll
    for (int i = 0; i < 3; i++)
        #pragma unroll
        for (int jj = 0; jj < 4; jj++)
            #pragma unroll
            for (int k = 0; k < 4; k++) acc[i][jj][k] = 0.0f;

    for (int j = 0; j < NCHUNK; j++) {
        const int tile = j / 9;
        const int kc = j - tile*9;

        // committed = min(j,33)+3; need chunk j done
        if      (j <= 33) asm volatile("cp.async.wait_group 2;" ::: "memory");
        else if (j == 34) asm volatile("cp.async.wait_group 1;" ::: "memory");
        else              asm volatile("cp.async.wait_group 0;" ::: "memory");
        __syncthreads();

        if (j <= 32) issue(j + 3);

        uint32_t a[3][4];
        #pragma unroll
        for (int mt = 0; mt < 3; mt++)
            ldsm4(a[mt], AH + (uint32_t)((mt*16 + rA)*ASTR3 + (kc*16 + cA)*2));
        const uint32_t Bc = B0 + (uint32_t)((j & 3) * BBUF);
        uint32_t bf[2][4];
        #pragma unroll
        for (int ng = 0; ng < 2; ng++)
            ldsm4t(bf[ng], Bc + (uint32_t)(rB*BSTR + (nloc + ng*16 + cB)*2));

        #pragma unroll
        for (int mt = 0; mt < 3; mt++)
            #pragma unroll
            for (int ng = 0; ng < 2; ng++) {
                mma16816h(acc[mt][ng*2  ], a[mt], bf[ng][0], bf[ng][1]);
                mma16816h(acc[mt][ng*2+1], a[mt], bf[ng][2], bf[ng][3]);
            }

        // Tile complete -> epilogue + acc re-init (registers only, no barrier)
        if (kc == 8) {
            const int ntile = gtile*4 + tile;
            const int Hp = ntile*4 + (wid >> 1);
            #pragma unroll
            for (int mt = 0; mt < 3; mt++)
                #pragma unroll
                for (int g = 0; g < 4; g++) {
                    int Wp = (wid & 1)*32 + g*8 + ecol;
                    int Cp = mt*16 + erow;
                    float* op = out + ((((size_t)b*NC + Cp)*IMG + (size_t)p*WSZ + Hp)*IMG
                                       + (size_t)q*WSZ + Wp);
                    *(float2*)op = make_float2(acc[mt][g][0], acc[mt][g][1]);
                    float* op2 = op + (size_t)8*IMG*IMG;   // Cp+8
                    *(float2*)op2 = make_float2(acc[mt][g][2], acc[mt][g][3]);
                    acc[mt][g][0] = 0.0f; acc[mt][g][1] = 0.0f;
                    acc[mt][g][2] = 0.0f; acc[mt][g][3] = 0.0f;
                }
        }
    }
}

extern "C" void kernel_launch(void* const* d_in, const int* in_sizes, int n_in,
                              void* d_out, int out_size)
{
    const float* x  = (const float*)d_in[0];
    const float* Ws = (const float*)d_in[1];
    const float* Hs = (const float*)d_in[2];
    const float* Cs = (const float*)d_in[3];
    float* out = (float*)d_out;

    cudaFuncSetAttribute(k_stage12, cudaFuncAttributeMaxDynamicSharedMemorySize,
                         SM12_TOTAL);
    cudaFuncSetAttribute(k_stage3, cudaFuncAttributeMaxDynamicSharedMemorySize,
                         SM3_TOTAL);

    k_prep<<<48, 256>>>(Ws, Hs, Cs);

    dim3 gA(64, NC/4, NB);                // 3072 CTAs
    k_stage12<<<gA, 256, SM12_TOTAL>>>(x);

    dim3 gB(4, NWIN);                     // 1024 CTAs
    k_stage3<<<gB, 256, SM3_TOTAL>>>(out);
}